// round 2
// baseline (speedup 1.0000x reference)
#include <cuda_runtime.h>
#include <cuda_bf16.h>
#include <math.h>

// Problem-size maxima: 100k nodes, 3.2M edges, 1000 graphs
#define MAXN 100000
#define MAXE 3200000
#define MAXG 1000

// Scratch (static __device__ arrays — no allocation allowed)
__device__ float g_dis[MAXN];          // deg accumulator, then rsqrt(deg)
__device__ float g_agg3[MAXN * 4];     // layer-1 pre-aggregation in x-space (padded)
__device__ float g_hw2[MAXN * 16];     // relu(h1) @ W2 per node
__device__ float g_h2[MAXN * 16];      // layer-2 neighbor aggregation
__device__ float g_pool[MAXG * 16];    // per-graph pooled features

// ---------------------------------------------------------------------------
// init: deg=1 (self loop), zero agg3 / h2 / pool
__global__ void k_init(int n_nodes, int n_graphs) {
    int total = n_nodes * 16;
    for (int i = blockIdx.x * blockDim.x + threadIdx.x; i < total;
         i += gridDim.x * blockDim.x) {
        g_h2[i] = 0.0f;
        if (i < n_nodes) g_dis[i] = 1.0f;
        if (i < n_nodes * 4) g_agg3[i] = 0.0f;
        if (i < n_graphs * 16) g_pool[i] = 0.0f;
    }
}

// deg: +1 per edge targeting col  (edge_index is int32: [2, E])
__global__ void k_deg(const int* __restrict__ ei, int n_edges) {
    int e = blockIdx.x * blockDim.x + threadIdx.x;
    if (e >= n_edges) return;
    int c = ei[n_edges + e];   // col = edge_index[1]
    atomicAdd(&g_dis[c], 1.0f);
}

__global__ void k_rsqrt(int n_nodes) {
    int i = blockIdx.x * blockDim.x + threadIdx.x;
    if (i >= n_nodes) return;
    g_dis[i] = rsqrtf(g_dis[i]);    // deg >= 1 always (self loop)
}

// Layer-1 scatter in RAW x-space (3 atomics/edge instead of 16):
// agg3[c] += norm * x[r]
__global__ void k_scatter1(const int* __restrict__ ei,
                           const float* __restrict__ x, int n_edges) {
    int e = blockIdx.x * blockDim.x + threadIdx.x;
    if (e >= n_edges) return;
    int r = ei[e];
    int c = ei[n_edges + e];
    float nrm = g_dis[r] * g_dis[c];
    const float* xr = x + (long)r * 3;
    float* dst = g_agg3 + (long)c * 4;
    atomicAdd(dst + 0, nrm * xr[0]);
    atomicAdd(dst + 1, nrm * xr[1]);
    atomicAdd(dst + 2, nrm * xr[2]);
}

// Per-node: finish layer 1 (add self loop, @W1, +b1, relu) and precompute
// hw2 = relu(h1) @ W2 for the layer-2 scatter.
__global__ void k_node(const float* __restrict__ x,
                       const float* __restrict__ W1,  // [3,16]
                       const float* __restrict__ b1,  // [16]
                       const float* __restrict__ W2,  // [16,16]
                       int n_nodes) {
    __shared__ float sW1[48];
    __shared__ float sb1[16];
    __shared__ float sW2[256];
    for (int t = threadIdx.x; t < 48; t += blockDim.x) sW1[t] = W1[t];
    for (int t = threadIdx.x; t < 16; t += blockDim.x) sb1[t] = b1[t];
    for (int t = threadIdx.x; t < 256; t += blockDim.x) sW2[t] = W2[t];
    __syncthreads();

    int i = blockIdx.x * blockDim.x + threadIdx.x;
    if (i >= n_nodes) return;

    float d = g_dis[i];
    float d2 = d * d;                 // self-loop norm
    float v0 = g_agg3[i * 4 + 0] + d2 * x[(long)i * 3 + 0];
    float v1 = g_agg3[i * 4 + 1] + d2 * x[(long)i * 3 + 1];
    float v2 = g_agg3[i * 4 + 2] + d2 * x[(long)i * 3 + 2];

    float h1[16];
#pragma unroll
    for (int j = 0; j < 16; j++) {
        float s = sb1[j] + v0 * sW1[j] + v1 * sW1[16 + j] + v2 * sW1[32 + j];
        h1[j] = fmaxf(s, 0.0f);
    }
    float* out = g_hw2 + (long)i * 16;
#pragma unroll
    for (int j = 0; j < 16; j++) {
        float s = 0.0f;
#pragma unroll
        for (int k = 0; k < 16; k++) s = fmaf(h1[k], sW2[k * 16 + j], s);
        out[j] = s;
    }
}

// Layer-2 scatter: h2[c] += norm * hw2[r]   (16 atomics/edge)
__global__ void k_scatter2(const int* __restrict__ ei, int n_edges) {
    int e = blockIdx.x * blockDim.x + threadIdx.x;
    if (e >= n_edges) return;
    int r = ei[e];
    int c = ei[n_edges + e];
    float nrm = g_dis[r] * g_dis[c];
    const float4* src = (const float4*)(g_hw2 + (long)r * 16);
    float* dst = g_h2 + (long)c * 16;
#pragma unroll
    for (int q = 0; q < 4; q++) {
        float4 v = src[q];
        atomicAdd(dst + q * 4 + 0, nrm * v.x);
        atomicAdd(dst + q * 4 + 1, nrm * v.y);
        atomicAdd(dst + q * 4 + 2, nrm * v.z);
        atomicAdd(dst + q * 4 + 3, nrm * v.w);
    }
}

// Pool: per (node, feature) thread; add self loop contribution + b2, then
// atomic into the graph accumulator.
__global__ void k_pool(const int* __restrict__ batch,
                       const float* __restrict__ b2, int n_nodes) {
    int t = blockIdx.x * blockDim.x + threadIdx.x;
    if (t >= n_nodes * 16) return;
    int i = t >> 4;
    int k = t & 15;
    int b = batch[i];
    float d = g_dis[i];
    float val = g_h2[t] + d * d * g_hw2[t] + b2[k];
    atomicAdd(&g_pool[b * 16 + k], val);
}

// Final: logits = g @ Wl + bl, log_softmax. One thread per graph.
__global__ void k_final(const float* __restrict__ Wl,  // [16,7]
                        const float* __restrict__ bl,  // [7]
                        float* __restrict__ out, int n_graphs) {
    int t = blockIdx.x * blockDim.x + threadIdx.x;
    if (t >= n_graphs) return;
    float gi[16];
#pragma unroll
    for (int k = 0; k < 16; k++) gi[k] = g_pool[t * 16 + k];
    float l[7];
    float m = -1e30f;
#pragma unroll
    for (int j = 0; j < 7; j++) {
        float s = bl[j];
#pragma unroll
        for (int k = 0; k < 16; k++) s = fmaf(gi[k], Wl[k * 7 + j], s);
        l[j] = s;
        m = fmaxf(m, s);
    }
    float sum = 0.0f;
#pragma unroll
    for (int j = 0; j < 7; j++) sum += expf(l[j] - m);
    float lse = m + logf(sum);
#pragma unroll
    for (int j = 0; j < 7; j++) out[t * 7 + j] = l[j] - lse;
}

// ---------------------------------------------------------------------------
extern "C" void kernel_launch(void* const* d_in, const int* in_sizes, int n_in,
                              void* d_out, int out_size) {
    const float* x     = (const float*)d_in[0];   // [N,3] f32
    const int*   ei    = (const int*)d_in[1];     // [2,E] int64 -> int32 by harness
    // d_in[2] = edge_attr (unused by reference)
    const int*   batch = (const int*)d_in[3];     // [N] int32
    const float* W1    = (const float*)d_in[4];
    const float* b1    = (const float*)d_in[5];
    const float* W2    = (const float*)d_in[6];
    const float* b2    = (const float*)d_in[7];
    const float* Wl    = (const float*)d_in[8];
    const float* bl    = (const float*)d_in[9];
    float* out = (float*)d_out;

    int n_nodes  = in_sizes[0] / 3;
    int n_edges  = in_sizes[1] / 2;
    int n_graphs = out_size / 7;

    const int B = 256;
    int grid_init = (n_nodes * 16 + B - 1) / B;
    int grid_e    = (n_edges + B - 1) / B;
    int grid_n    = (n_nodes + B - 1) / B;
    int grid_nf   = (n_nodes * 16 + B - 1) / B;
    int grid_g    = (n_graphs + B - 1) / B;

    k_init<<<grid_init, B>>>(n_nodes, n_graphs);
    k_deg<<<grid_e, B>>>(ei, n_edges);
    k_rsqrt<<<grid_n, B>>>(n_nodes);
    k_scatter1<<<grid_e, B>>>(ei, x, n_edges);
    k_node<<<grid_n, B>>>(x, W1, b1, W2, n_nodes);
    k_scatter2<<<grid_e, B>>>(ei, n_edges);
    k_pool<<<grid_nf, B>>>(batch, b2, n_nodes);
    k_final<<<grid_g, B>>>(Wl, bl, out, n_graphs);
}

// round 4
// speedup vs baseline: 2.5443x; 2.5443x over previous
#include <cuda_runtime.h>
#include <cuda_bf16.h>
#include <math.h>

// Problem-size maxima: 100k nodes, 3.2M edges, 1000 graphs
#define MAXN 100000
#define MAXE 3200000
#define MAXG 1000

// Scratch (static __device__ arrays — no allocation allowed)
__device__ float g_dis[MAXN];                         // deg, then rsqrt(deg)
__device__ __align__(16) float g_y[MAXN * 4];         // dis[i]*x[i], padded to 4
__device__ __align__(16) float g_agg3[MAXN * 4];      // layer-1 agg: sum dis_r*x_r
__device__ __align__(16) float g_hw2[MAXN * 16];      // dis[i] * (relu(h1) @ W2)
__device__ __align__(16) float g_h2[MAXN * 16];       // layer-2 agg: sum hw2'_r
__device__ __align__(16) float g_pool[MAXG * 16];     // per-graph pooled features

__device__ __forceinline__ void red_add_v4(float* addr, float4 v) {
    asm volatile("red.global.add.v4.f32 [%0], {%1,%2,%3,%4};"
                 :: "l"(addr), "f"(v.x), "f"(v.y), "f"(v.z), "f"(v.w)
                 : "memory");
}

// ---------------------------------------------------------------------------
// init: deg=1 (self loop), zero agg3 / h2 / pool
__global__ void k_init(int n_nodes, int n_graphs) {
    int total = n_nodes * 16;
    for (int i = blockIdx.x * blockDim.x + threadIdx.x; i < total;
         i += gridDim.x * blockDim.x) {
        g_h2[i] = 0.0f;
        if (i < n_nodes) g_dis[i] = 1.0f;
        if (i < n_nodes * 4) g_agg3[i] = 0.0f;
        if (i < n_graphs * 16) g_pool[i] = 0.0f;
    }
}

// deg: +1 per edge targeting col
__global__ void k_deg(const int* __restrict__ ei, int n_edges) {
    int e = blockIdx.x * blockDim.x + threadIdx.x;
    if (e >= n_edges) return;
    atomicAdd(&g_dis[ei[n_edges + e]], 1.0f);
}

// dis = rsqrt(deg); y[i] = dis[i] * x[i] (padded float4)
__global__ void k_prep(const float* __restrict__ x, int n_nodes) {
    int i = blockIdx.x * blockDim.x + threadIdx.x;
    if (i >= n_nodes) return;
    float d = rsqrtf(g_dis[i]);     // deg >= 1 always
    g_dis[i] = d;
    const float* xr = x + (long)i * 3;
    ((float4*)g_y)[i] = make_float4(d * xr[0], d * xr[1], d * xr[2], 0.0f);
}

// Layer-1 scatter: agg3[c] += y[r]   (ONE red.v4 per edge)
__global__ void k_scatter1(const int* __restrict__ ei, int n_edges) {
    int e = blockIdx.x * blockDim.x + threadIdx.x;
    if (e >= n_edges) return;
    int r = ei[e];
    int c = ei[n_edges + e];
    float4 v = ((const float4*)g_y)[r];
    red_add_v4(g_agg3 + (long)c * 4, v);
}

// Per-node: h1 = relu(b1 + dis_c*(agg + dis_c*x) @ W1);  hw2' = dis * (h1@W2)
__global__ void k_node(const float* __restrict__ x,
                       const float* __restrict__ W1,  // [3,16]
                       const float* __restrict__ b1,  // [16]
                       const float* __restrict__ W2,  // [16,16]
                       int n_nodes) {
    __shared__ float sW1[48];
    __shared__ float sb1[16];
    __shared__ float sW2[256];
    for (int t = threadIdx.x; t < 48; t += blockDim.x) sW1[t] = W1[t];
    for (int t = threadIdx.x; t < 16; t += blockDim.x) sb1[t] = b1[t];
    for (int t = threadIdx.x; t < 256; t += blockDim.x) sW2[t] = W2[t];
    __syncthreads();

    int i = blockIdx.x * blockDim.x + threadIdx.x;
    if (i >= n_nodes) return;

    float d = g_dis[i];
    // v = d * (sum_r dis_r x_r  +  d * x_i)    (self loop folded in)
    float4 a = ((const float4*)g_agg3)[i];
    const float* xr = x + (long)i * 3;
    float v0 = d * (a.x + d * xr[0]);
    float v1 = d * (a.y + d * xr[1]);
    float v2 = d * (a.z + d * xr[2]);

    float h1[16];
#pragma unroll
    for (int j = 0; j < 16; j++) {
        float s = sb1[j] + v0 * sW1[j] + v1 * sW1[16 + j] + v2 * sW1[32 + j];
        h1[j] = fmaxf(s, 0.0f);
    }
    float* out = g_hw2 + (long)i * 16;
#pragma unroll
    for (int j = 0; j < 16; j++) {
        float s = 0.0f;
#pragma unroll
        for (int k = 0; k < 16; k++) s = fmaf(h1[k], sW2[k * 16 + j], s);
        out[j] = d * s;                 // fold source-side dis
    }
}

// Layer-2 scatter: h2[c] += hw2'[r]   (FOUR red.v4 per edge)
__global__ void k_scatter2(const int* __restrict__ ei, int n_edges) {
    int e = blockIdx.x * blockDim.x + threadIdx.x;
    if (e >= n_edges) return;
    int r = ei[e];
    int c = ei[n_edges + e];
    const float4* src = (const float4*)g_hw2 + (long)r * 4;
    float* dst = g_h2 + (long)c * 16;
    float4 v0 = src[0], v1 = src[1], v2 = src[2], v3 = src[3];
    red_add_v4(dst + 0,  v0);
    red_add_v4(dst + 4,  v1);
    red_add_v4(dst + 8,  v2);
    red_add_v4(dst + 12, v3);
}

// Pool: val = dis_c*(agg + hw2'_c) + b2; red.v4 into graph accumulator.
__global__ void k_pool(const int* __restrict__ batch,
                       const float* __restrict__ b2, int n_nodes) {
    int t = blockIdx.x * blockDim.x + threadIdx.x;
    if (t >= n_nodes * 4) return;
    int i = t >> 2;
    int q = t & 3;
    int b = batch[i];
    float d = g_dis[i];
    float4 s = ((const float4*)g_h2)[t];
    float4 w = ((const float4*)g_hw2)[t];
    // h2_final = d*(S + hw2') ; + b2 once per node
    float4 v = make_float4(d * (s.x + w.x) + b2[q * 4 + 0],
                           d * (s.y + w.y) + b2[q * 4 + 1],
                           d * (s.z + w.z) + b2[q * 4 + 2],
                           d * (s.w + w.w) + b2[q * 4 + 3]);
    red_add_v4(g_pool + (long)b * 16 + q * 4, v);
}

// Final: logits = g @ Wl + bl, log_softmax. One thread per graph.
__global__ void k_final(const float* __restrict__ Wl,  // [16,7]
                        const float* __restrict__ bl,  // [7]
                        float* __restrict__ out, int n_graphs) {
    int t = blockIdx.x * blockDim.x + threadIdx.x;
    if (t >= n_graphs) return;
    float gi[16];
#pragma unroll
    for (int k = 0; k < 16; k++) gi[k] = g_pool[t * 16 + k];
    float l[7];
    float m = -1e30f;
#pragma unroll
    for (int j = 0; j < 7; j++) {
        float s = bl[j];
#pragma unroll
        for (int k = 0; k < 16; k++) s = fmaf(gi[k], Wl[k * 7 + j], s);
        l[j] = s;
        m = fmaxf(m, s);
    }
    float sum = 0.0f;
#pragma unroll
    for (int j = 0; j < 7; j++) sum += expf(l[j] - m);
    float lse = m + logf(sum);
#pragma unroll
    for (int j = 0; j < 7; j++) out[t * 7 + j] = l[j] - lse;
}

// ---------------------------------------------------------------------------
extern "C" void kernel_launch(void* const* d_in, const int* in_sizes, int n_in,
                              void* d_out, int out_size) {
    const float* x     = (const float*)d_in[0];   // [N,3] f32
    const int*   ei    = (const int*)d_in[1];     // [2,E] (int64 -> int32 by harness)
    // d_in[2] = edge_attr (unused by reference)
    const int*   batch = (const int*)d_in[3];     // [N] int32
    const float* W1    = (const float*)d_in[4];
    const float* b1    = (const float*)d_in[5];
    const float* W2    = (const float*)d_in[6];
    const float* b2    = (const float*)d_in[7];
    const float* Wl    = (const float*)d_in[8];
    const float* bl    = (const float*)d_in[9];
    float* out = (float*)d_out;

    int n_nodes  = in_sizes[0] / 3;
    int n_edges  = in_sizes[1] / 2;
    int n_graphs = out_size / 7;

    const int B = 256;
    int grid_init = (n_nodes * 16 + B - 1) / B;
    int grid_e    = (n_edges + B - 1) / B;
    int grid_n    = (n_nodes + B - 1) / B;
    int grid_n4   = (n_nodes * 4 + B - 1) / B;
    int grid_g    = (n_graphs + B - 1) / B;

    k_init<<<grid_init, B>>>(n_nodes, n_graphs);
    k_deg<<<grid_e, B>>>(ei, n_edges);
    k_prep<<<grid_n, B>>>(x, n_nodes);
    k_scatter1<<<grid_e, B>>>(ei, n_edges);
    k_node<<<grid_n, B>>>(x, W1, b1, W2, n_nodes);
    k_scatter2<<<grid_e, B>>>(ei, n_edges);
    k_pool<<<grid_n4, B>>>(batch, b2, n_nodes);
    k_final<<<grid_g, B>>>(Wl, bl, out, n_graphs);
}

// round 5
// speedup vs baseline: 3.0259x; 1.1893x over previous
#include <cuda_runtime.h>
#include <cuda_bf16.h>
#include <math.h>

// Problem-size maxima: 100k nodes, 3.2M edges, 1000 graphs
#define MAXN 100000
#define MAXE 3200000
#define MAXG 1000

// Scratch (static __device__ arrays — no allocation allowed)
__device__ int   g_cnt[MAXN];                      // in-degree histogram (CSR lengths)
__device__ int   g_cnt2[MAXN];                     // reorder position counters
__device__ int   g_rowptr[MAXN];                   // CSR exclusive offsets
__device__ int   g_part[1024];                     // scan partials
__device__ int   g_src[MAXE];                      // edge sources sorted by dest
__device__ float g_dis[MAXN];                      // rsqrt(deg)
__device__ __align__(16) float g_y[MAXN * 4];      // dis[i]*x[i], padded to 4
__device__ __align__(16) float g_agg3[MAXN * 4];   // layer-1 aggregation
__device__ __align__(16) float g_hw2[MAXN * 16];   // dis[i] * (relu(h1) @ W2)
__device__ __align__(16) float g_pool[MAXG * 16];  // per-graph pooled features

__device__ __forceinline__ void red_add_v4(float* addr, float4 v) {
    asm volatile("red.global.add.v4.f32 [%0], {%1,%2,%3,%4};"
                 :: "l"(addr), "f"(v.x), "f"(v.y), "f"(v.z), "f"(v.w)
                 : "memory");
}

// ---------------------------------------------------------------------------
__global__ void k_init(int n_nodes, int n_graphs) {
    for (int i = blockIdx.x * blockDim.x + threadIdx.x; i < n_nodes;
         i += gridDim.x * blockDim.x) {
        g_cnt[i] = 0;
        g_cnt2[i] = 0;
        if (i < n_graphs * 16) g_pool[i] = 0.0f;
    }
}

// in-degree histogram over col
__global__ void k_deg(const int* __restrict__ ei, int n_edges) {
    int e = blockIdx.x * blockDim.x + threadIdx.x;
    if (e >= n_edges) return;
    atomicAdd(&g_cnt[ei[n_edges + e]], 1);
}

// ---- 3-kernel exclusive scan of g_cnt -> g_rowptr --------------------------
__global__ void k_scan1(int n) {
    __shared__ int warp_sums[32];
    int i = blockIdx.x * 1024 + threadIdx.x;
    int lane = threadIdx.x & 31, wid = threadIdx.x >> 5;
    int v = (i < n) ? g_cnt[i] : 0;
    int s = v;
#pragma unroll
    for (int off = 1; off < 32; off <<= 1) {
        int t = __shfl_up_sync(~0u, s, off);
        if (lane >= off) s += t;
    }
    if (lane == 31) warp_sums[wid] = s;
    __syncthreads();
    if (wid == 0) {
        int ws = warp_sums[lane];
#pragma unroll
        for (int off = 1; off < 32; off <<= 1) {
            int t = __shfl_up_sync(~0u, ws, off);
            if (lane >= off) ws += t;
        }
        warp_sums[lane] = ws;
    }
    __syncthreads();
    int excl = s - v + (wid > 0 ? warp_sums[wid - 1] : 0);
    if (i < n) g_rowptr[i] = excl;
    if (threadIdx.x == 0) g_part[blockIdx.x] = warp_sums[31];
}

__global__ void k_scan2(int nb) {
    __shared__ int warp_sums[32];
    int t = threadIdx.x;
    int lane = t & 31, wid = t >> 5;
    int v = (t < nb) ? g_part[t] : 0;
    int s = v;
#pragma unroll
    for (int off = 1; off < 32; off <<= 1) {
        int u = __shfl_up_sync(~0u, s, off);
        if (lane >= off) s += u;
    }
    if (lane == 31) warp_sums[wid] = s;
    __syncthreads();
    if (wid == 0) {
        int ws = warp_sums[lane];
#pragma unroll
        for (int off = 1; off < 32; off <<= 1) {
            int u = __shfl_up_sync(~0u, ws, off);
            if (lane >= off) ws += u;
        }
        warp_sums[lane] = ws;
    }
    __syncthreads();
    if (t < nb) g_part[t] = s - v + (wid > 0 ? warp_sums[wid - 1] : 0);
}

__global__ void k_scan3(int n) {
    int i = blockIdx.x * blockDim.x + threadIdx.x;
    if (i < n) g_rowptr[i] += g_part[i >> 10];
}

// bucket edges by destination: g_src[rowptr[c] + pos] = r
__global__ void k_reorder(const int* __restrict__ ei, int n_edges) {
    int e = blockIdx.x * blockDim.x + threadIdx.x;
    if (e >= n_edges) return;
    int r = ei[e];
    int c = ei[n_edges + e];
    int p = atomicAdd(&g_cnt2[c], 1);
    g_src[g_rowptr[c] + p] = r;
}

// dis = rsqrt(1 + indeg); y[i] = dis[i]*x[i]
__global__ void k_prep(const float* __restrict__ x, int n_nodes) {
    int i = blockIdx.x * blockDim.x + threadIdx.x;
    if (i >= n_nodes) return;
    float d = rsqrtf(1.0f + (float)g_cnt[i]);
    g_dis[i] = d;
    const float* xr = x + (long)i * 3;
    ((float4*)g_y)[i] = make_float4(d * xr[0], d * xr[1], d * xr[2], 0.0f);
}

// Layer-1 gather: warp per node, agg3[i] = sum_{r in N(i)} y[r]
__global__ void k_gather1(int n_nodes) {
    int w = (blockIdx.x * blockDim.x + threadIdx.x) >> 5;
    if (w >= n_nodes) return;
    int lane = threadIdx.x & 31;
    int start = g_rowptr[w], len = g_cnt[w];
    float4 acc = make_float4(0.f, 0.f, 0.f, 0.f);
    for (int j = lane; j < len; j += 32) {
        float4 v = ((const float4*)g_y)[g_src[start + j]];
        acc.x += v.x; acc.y += v.y; acc.z += v.z; acc.w += v.w;
    }
#pragma unroll
    for (int m = 16; m >= 1; m >>= 1) {
        acc.x += __shfl_xor_sync(~0u, acc.x, m);
        acc.y += __shfl_xor_sync(~0u, acc.y, m);
        acc.z += __shfl_xor_sync(~0u, acc.z, m);
    }
    if (lane == 0) ((float4*)g_agg3)[w] = acc;
}

// Per-node dense math: h1 = relu(b1 + d*(agg + d*x)@W1); hw2' = d*(h1@W2)
__global__ void k_node(const float* __restrict__ x,
                       const float* __restrict__ W1,  // [3,16]
                       const float* __restrict__ b1,  // [16]
                       const float* __restrict__ W2,  // [16,16]
                       int n_nodes) {
    __shared__ float sW1[48];
    __shared__ float sb1[16];
    __shared__ float sW2[256];
    for (int t = threadIdx.x; t < 48; t += blockDim.x) sW1[t] = W1[t];
    for (int t = threadIdx.x; t < 16; t += blockDim.x) sb1[t] = b1[t];
    for (int t = threadIdx.x; t < 256; t += blockDim.x) sW2[t] = W2[t];
    __syncthreads();

    int i = blockIdx.x * blockDim.x + threadIdx.x;
    if (i >= n_nodes) return;

    float d = g_dis[i];
    float4 a = ((const float4*)g_agg3)[i];
    const float* xr = x + (long)i * 3;
    float v0 = d * (a.x + d * xr[0]);
    float v1 = d * (a.y + d * xr[1]);
    float v2 = d * (a.z + d * xr[2]);

    float h1[16];
#pragma unroll
    for (int j = 0; j < 16; j++) {
        float s = sb1[j] + v0 * sW1[j] + v1 * sW1[16 + j] + v2 * sW1[32 + j];
        h1[j] = fmaxf(s, 0.0f);
    }
    float* out = g_hw2 + (long)i * 16;
#pragma unroll
    for (int j = 0; j < 16; j++) {
        float s = 0.0f;
#pragma unroll
        for (int k = 0; k < 16; k++) s = fmaf(h1[k], sW2[k * 16 + j], s);
        out[j] = d * s;                 // fold source-side dis
    }
}

// Layer-2 gather + pool fused: warp per node.
// 4 lanes per edge (q = lane&3 selects float4 chunk), 8 edges in flight.
__global__ void k_gather2pool(const int* __restrict__ batch,
                              const float* __restrict__ b2, int n_nodes) {
    int w = (blockIdx.x * blockDim.x + threadIdx.x) >> 5;
    if (w >= n_nodes) return;
    int lane = threadIdx.x & 31;
    int grp = lane >> 2, q = lane & 3;
    int start = g_rowptr[w], len = g_cnt[w];
    float4 acc = make_float4(0.f, 0.f, 0.f, 0.f);
    for (int j = grp; j < len; j += 8) {
        int src = g_src[start + j];
        float4 v = ((const float4*)g_hw2)[(long)src * 4 + q];
        acc.x += v.x; acc.y += v.y; acc.z += v.z; acc.w += v.w;
    }
    // reduce across the 8 groups (lane strides of 4): xor 16, 8, 4
#pragma unroll
    for (int m = 16; m >= 4; m >>= 1) {
        acc.x += __shfl_xor_sync(~0u, acc.x, m);
        acc.y += __shfl_xor_sync(~0u, acc.y, m);
        acc.z += __shfl_xor_sync(~0u, acc.z, m);
        acc.w += __shfl_xor_sync(~0u, acc.w, m);
    }
    if (lane < 4) {                     // lane == q
        float d = g_dis[w];
        float4 ws = ((const float4*)g_hw2)[(long)w * 4 + lane];  // self loop
        float4 bb = ((const float4*)b2)[lane];
        float4 v = make_float4(d * (acc.x + ws.x) + bb.x,
                               d * (acc.y + ws.y) + bb.y,
                               d * (acc.z + ws.z) + bb.z,
                               d * (acc.w + ws.w) + bb.w);
        red_add_v4(g_pool + (long)batch[w] * 16 + lane * 4, v);
    }
}

// Final: logits = g @ Wl + bl, log_softmax. One thread per graph.
__global__ void k_final(const float* __restrict__ Wl,  // [16,7]
                        const float* __restrict__ bl,  // [7]
                        float* __restrict__ out, int n_graphs) {
    int t = blockIdx.x * blockDim.x + threadIdx.x;
    if (t >= n_graphs) return;
    float gi[16];
#pragma unroll
    for (int k = 0; k < 16; k++) gi[k] = g_pool[t * 16 + k];
    float l[7];
    float m = -1e30f;
#pragma unroll
    for (int j = 0; j < 7; j++) {
        float s = bl[j];
#pragma unroll
        for (int k = 0; k < 16; k++) s = fmaf(gi[k], Wl[k * 7 + j], s);
        l[j] = s;
        m = fmaxf(m, s);
    }
    float sum = 0.0f;
#pragma unroll
    for (int j = 0; j < 7; j++) sum += expf(l[j] - m);
    float lse = m + logf(sum);
#pragma unroll
    for (int j = 0; j < 7; j++) out[t * 7 + j] = l[j] - lse;
}

// ---------------------------------------------------------------------------
extern "C" void kernel_launch(void* const* d_in, const int* in_sizes, int n_in,
                              void* d_out, int out_size) {
    const float* x     = (const float*)d_in[0];   // [N,3] f32
    const int*   ei    = (const int*)d_in[1];     // [2,E] (int64 -> int32 by harness)
    // d_in[2] = edge_attr (unused by reference)
    const int*   batch = (const int*)d_in[3];     // [N] int32
    const float* W1    = (const float*)d_in[4];
    const float* b1    = (const float*)d_in[5];
    const float* W2    = (const float*)d_in[6];
    const float* b2    = (const float*)d_in[7];
    const float* Wl    = (const float*)d_in[8];
    const float* bl    = (const float*)d_in[9];
    float* out = (float*)d_out;

    int n_nodes  = in_sizes[0] / 3;
    int n_edges  = in_sizes[1] / 2;
    int n_graphs = out_size / 7;

    const int B = 256;
    int grid_n  = (n_nodes + B - 1) / B;
    int grid_e  = (n_edges + B - 1) / B;
    int grid_g  = (n_graphs + B - 1) / B;
    int grid_w  = (n_nodes * 32 + B - 1) / B;     // warp per node
    int nb      = (n_nodes + 1023) / 1024;

    k_init<<<grid_n, B>>>(n_nodes, n_graphs);
    k_deg<<<grid_e, B>>>(ei, n_edges);
    k_scan1<<<nb, 1024>>>(n_nodes);
    k_scan2<<<1, 1024>>>(nb);
    k_scan3<<<grid_n, B>>>(n_nodes);
    k_reorder<<<grid_e, B>>>(ei, n_edges);
    k_prep<<<grid_n, B>>>(x, n_nodes);
    k_gather1<<<grid_w, B>>>(n_nodes);
    k_node<<<grid_n, B>>>(x, W1, b1, W2, n_nodes);
    k_gather2pool<<<grid_w, B>>>(batch, b2, n_nodes);
    k_final<<<grid_g, B>>>(Wl, bl, out, n_graphs);
}